// round 16
// baseline (speedup 1.0000x reference)
#include <cuda_runtime.h>
#include <cuda_fp16.h>
#include <math.h>

#define Bb 64
#define Tt 512
#define Ii 128
#define Rr 2048
#define Hh 512
#define Oo 128
#define KE 2176
#define KG 640
#define MG 1536
#define NBLK 140
#define NBE 112
#define NBG 28
#define NTHR 512
#define BCH_BYTES 18432                 // B ring chunk: k=64 = 4 subs x (hi+lo) x 2304B
#define BRING_BYTES (4*BCH_BYTES)       // 73728
#define WSUB_HALFS 3072                 // W per 16-k sub: 128 rows x 24 halfs
#define SMEM_BYTES (BRING_BYTES + 20*6144)  // 196608

typedef __half hf;

// ---------------- device scratch ----------------
__device__ hf WEH[Rr*KE];                  // ESN weights^T fp16 [c][k]
__device__ hf WGH[MG*KG];                  // GRU weights^T fp16 [m][k]
__device__ hf Xh[Tt*Ii*Bb], Xl[Tt*Ii*Bb];  // x transposed hi/lo [t][i][b]
__device__ hf HEh[Rr*Bb], HEl[Rr*Bb];      // ESN state fp16 hi/lo [k][b]
__device__ hf HGh[Hh*Bb], HGl[Hh*Bb];      // GRU state fp16 hi/lo [j][b]
__device__ float hET[Rr*Bb], hGT[Hh*Bb];   // fp32 states (transposed)
__device__ float accE[14][Rr*Bb];          // ESN partials: 7 K-splits x 2 warp-parities
__device__ float accRZ[4][1024*Bb];        // GRU r,z partials: 2 K-splits x 2 parities
__device__ float accNH[4][Hh*Bb];          // GRU n-gate h-part: 2 x 2
__device__ float accNX[2][Hh*Bb];          // GRU n-gate x-part: 2 parities
__device__ unsigned g_ctrE, g_ctrG;
__device__ float g_hE[Bb*Rr], g_hG[Bb*Hh];
__device__ float g_proj[Bb*Hh], g_cat[Bb*2*Hh], g_gate[Bb*Hh], g_comb[Bb*Hh], g_hid[Bb*Hh];

__device__ __forceinline__ float sigm(float x){ return 1.0f/(1.0f+expf(-x)); }
__device__ __forceinline__ float fsig(float x){ return __fdividef(1.0f, 1.0f + __expf(-x)); }
__device__ __forceinline__ float ftanh(float x){
    float e = __expf(2.0f*x);
    return 1.0f - __fdividef(2.0f, e + 1.0f);
}
__device__ __forceinline__ void hsplit(float v, hf* ph, hf* pl){
    hf h = __float2half_rn(v); *ph = h; *pl = __float2half_rn(v - __half2float(h));
}
__device__ __forceinline__ unsigned hp2(hf a, hf b){
    return (unsigned)__half_as_ushort(a) | ((unsigned)__half_as_ushort(b) << 16);
}
__device__ __forceinline__ void hpack4(float v0,float v1,float v2,float v3, hf* dh, hf* dl){
    hf h0=__float2half_rn(v0), h1=__float2half_rn(v1), h2=__float2half_rn(v2), h3=__float2half_rn(v3);
    hf l0=__float2half_rn(v0-__half2float(h0));
    hf l1=__float2half_rn(v1-__half2float(h1));
    hf l2=__float2half_rn(v2-__half2float(h2));
    hf l3=__float2half_rn(v3-__half2float(h3));
    *(uint2*)dh = make_uint2(hp2(h0,h1), hp2(h2,h3));
    *(uint2*)dl = make_uint2(hp2(l0,l1), hp2(l2,l3));
}
__device__ __forceinline__ void ldsm4(unsigned* r, const hf* p){
    unsigned a = (unsigned)__cvta_generic_to_shared(p);
    asm volatile("ldmatrix.sync.aligned.m8n8.x4.shared.b16 {%0,%1,%2,%3},[%4];"
        : "=r"(r[0]),"=r"(r[1]),"=r"(r[2]),"=r"(r[3]) : "r"(a));
}
__device__ __forceinline__ void ldsm4t(unsigned* r, const hf* p){
    unsigned a = (unsigned)__cvta_generic_to_shared(p);
    asm volatile("ldmatrix.sync.aligned.m8n8.x4.trans.shared.b16 {%0,%1,%2,%3},[%4];"
        : "=r"(r[0]),"=r"(r[1]),"=r"(r[2]),"=r"(r[3]) : "r"(a));
}
__device__ __forceinline__ void mma_hf(float* d, const unsigned* a, const unsigned* b){
    asm volatile("mma.sync.aligned.m16n8k16.row.col.f32.f16.f16.f32 "
        "{%0,%1,%2,%3},{%4,%5,%6,%7},{%8,%9},{%0,%1,%2,%3};"
        : "+f"(d[0]),"+f"(d[1]),"+f"(d[2]),"+f"(d[3])
        : "r"(a[0]),"r"(a[1]),"r"(a[2]),"r"(a[3]),"r"(b[0]),"r"(b[1]));
}
__device__ __forceinline__ void cp16(unsigned dst, const void* src){
    asm volatile("cp.async.cg.shared.global [%0],[%1],16;" :: "r"(dst),"l"(src));
}

// ---------------- prep ----------------
__global__ void k_prepWE(const float* __restrict__ Wres, const float* __restrict__ Win){
    int idx = blockIdx.x*blockDim.x + threadIdx.x;        // c*KE + k
    int c = idx/KE, k = idx - c*KE;
    float w = (k < Rr) ? Wres[k*Rr + c] : Win[(k-Rr)*Rr + c];
    WEH[idx] = __float2half_rn(w);
}
__global__ void k_prepWG(const float* __restrict__ Whh, const float* __restrict__ Wih){
    int idx = blockIdx.x*blockDim.x + threadIdx.x;        // m*KG + k
    int m = idx/KG, k = idx - m*KG;
    float w = (k < Hh) ? Whh[m*Hh + k] : Wih[m*Ii + (k-Hh)];
    WGH[idx] = __float2half_rn(w);
}
__global__ void k_prepXI(const float* __restrict__ x){
    int idx = blockIdx.x*blockDim.x + threadIdx.x;        // t*8192 + i*64 + b
    int t = idx >> 13, r = idx & 8191, i = r >> 6, b = r & 63;
    hsplit(x[b*(Tt*Ii) + t*Ii + i], &Xh[idx], &Xl[idx]);
    hf z = __float2half_rn(0.0f);
    if(idx == 0){ g_ctrE = 0u; g_ctrG = 0u; }
    if(idx < Rr*Bb){ hET[idx]=0.0f; HEh[idx]=z; HEl[idx]=z; }
    if(idx < Hh*Bb){ hGT[idx]=0.0f; HGh[idx]=z; HGl[idx]=z; }
}

__device__ __forceinline__ void gbar(unsigned* ctr, unsigned target){
    __threadfence();
    __syncthreads();
    if(threadIdx.x == 0){
        atomicAdd(ctr, 1u);
        volatile unsigned* p = ctr;
        while(*p < target) __nanosleep(32);
    }
    __syncthreads();
    __threadfence();
}

// ---------------- persistent all-timesteps kernel ----------------
// 140 blocks x 512 thr. Warp = (k-parity, m32 group, n32 half): each warp
// computes an m32 x n32 tile over its parity's k16-subs (16 HMMA/sub,
// 32 acc regs). k-partner warps write disjoint acc slots; epilogue sums.
// ESN group (112 blocks) and GRU group (28) use separate spin counters.
__global__ void __launch_bounds__(NTHR) k_all(
    const float* __restrict__ bih, const float* __restrict__ bhh)
{
    extern __shared__ __align__(16) hf sm[];
    const int tid = threadIdx.x, lane = tid & 31, wid = tid >> 5, bx = blockIdx.x;
    const unsigned sb = (unsigned)__cvta_generic_to_shared(sm);
    const bool isE = (bx < NBE);
    const int kpar = wid & 1;             // k16-sub parity
    const int tile = wid >> 1;            // 0..7
    const int mg   = tile >> 1;           // m32 group 0..3
    const int nh   = tile & 1;            // n32 half

    // ---- role setup ----
    const hf *Wp, *Bh, *Bl; float* acc; int Kst, kbase, nch, kth;
    if(isE){
        int m0 = (bx/7)*128, ks = bx%7;
        kbase = ks*320; nch = (ks < 6) ? 5 : 4; kth = Rr; Kst = KE;
        Wp = WEH + (size_t)m0*KE;
        Bh = HEh; Bl = HEl; acc = accE[ks*2 + kpar] + m0*Bb;
    } else if(bx < 128){
        int g = bx-112, m0 = (g>>1)*128, ks = g&1;
        kbase = ks*320; nch = 5; kth = Hh; Kst = KG;
        Wp = WGH + (size_t)m0*KG;
        Bh = HGh; Bl = HGl; acc = accRZ[ks*2 + kpar] + m0*Bb;
    } else if(bx < 136){
        int g = bx-128, mt = g>>1, ks = g&1;
        kbase = ks*256; nch = 4; kth = Hh; Kst = KG;
        Wp = WGH + (size_t)(1024 + mt*128)*KG;
        Bh = HGh; Bl = HGl; acc = accNH[ks*2 + kpar] + mt*128*Bb;
    } else {
        int mt = bx-136;
        kbase = 512; nch = 2; kth = Hh; Kst = KG;
        Wp = WGH + (size_t)(1024 + mt*128)*KG;
        Bh = HGh; Bl = HGl; acc = accNX[kpar] + mt*128*Bb;
    }
    unsigned* ctr = isE ? &g_ctrE : &g_ctrG;
    const unsigned NB = isE ? NBE : NBG;

    // ---- one-time W prologue: nch*4 subs, each 128 rows x 24-half stride ----
    {
        const int nsubs = nch*4;
        int rp = tid & 255, row = rp >> 1, part = rp & 1;
        for(int s2 = 0; s2 < nsubs; s2 += 2){
            int sub = s2 + (tid >> 8);
            if(sub < nsubs)
                cp16(sb + (unsigned)BRING_BYTES + (unsigned)(sub*6144 + row*48 + part*16),
                     Wp + (size_t)row*Kst + kbase + sub*16 + part*8);
        }
        asm volatile("cp.async.commit_group;");
        asm volatile("cp.async.wait_group 0;");
        __syncthreads();
    }

    // ---- B loader mapping: each thread does 2 cp16 per k=64 chunk ----
    const int bsub = tid >> 7, btid = tid & 127;
    const int krow = btid >> 3, boff = (btid & 7) * 8;
    const unsigned bd0 = sb + (unsigned)(bsub*4608 + krow*144 + (btid&7)*16);

    const int mw = mg*32;
    const int ar = lane & 15, ac = (lane>>4)*8;
    const int r4 = lane>>2, c2 = 2*(lane&3);
    const int gbaseE = bx*NTHR + tid;
    const int gbaseG = (bx - NBE)*NTHR + tid;
    const int NT_E = NBE*NTHR, NT_G = NBG*NTHR;

    for(int t = 0; t < Tt; t++){
        const hf* XtH = Xh + (size_t)t*Ii*Bb;
        const hf* XtL = Xl + (size_t)t*Ii*Bb;

        auto issue = [&](int c){
            if(c >= nch) return;
            unsigned dst = bd0 + (unsigned)(c & 3)*BCH_BYTES;
            int kr = kbase + c*64 + bsub*16 + krow;
            const hf* qh = (kr < kth) ? Bh + kr*Bb + boff : XtH + (kr-kth)*Bb + boff;
            const hf* ql = (kr < kth) ? Bl + kr*Bb + boff : XtL + (kr-kth)*Bb + boff;
            cp16(dst, qh);
            cp16(dst + 2304u, ql);
            asm volatile("cp.async.commit_group;");
        };

        float d[2][4][4];
        #pragma unroll
        for(int m=0;m<2;m++)
            #pragma unroll
            for(int j=0;j<4;j++)
                #pragma unroll
                for(int q=0;q<4;q++) d[m][j][q] = 0.0f;

        issue(0); issue(1); issue(2);

        for(int c = 0; c < nch; c++){
            if(c < nch-2)       asm volatile("cp.async.wait_group 2;");
            else if(c == nch-2) asm volatile("cp.async.wait_group 1;");
            else                asm volatile("cp.async.wait_group 0;");
            __syncthreads();
            if(c + 3 < nch) issue(c + 3);

            #pragma unroll
            for(int sp = 0; sp < 2; ++sp){
                const int sub = kpar + sp*2;
                const hf* sw  = sm + (BRING_BYTES/2) + (size_t)(c*4 + sub)*WSUB_HALFS;
                const hf* sbh = sm + (size_t)(c & 3)*(BCH_BYTES/2) + sub*2304;
                const hf* sbl = sbh + 1152;

                unsigned A[2][4], Bf[2][2][4];
                ldsm4(A[0], sw + (mw + ar)*24 + ac);
                ldsm4(A[1], sw + (mw + 16 + ar)*24 + ac);
                #pragma unroll
                for(int i=0; i<2; i++){
                    ldsm4t(Bf[0][i], sbh + ar*72 + (2*nh + i)*16 + ac);
                    ldsm4t(Bf[1][i], sbl + ar*72 + (2*nh + i)*16 + ac);
                }
                #pragma unroll
                for(int m=0; m<2; m++)
                    #pragma unroll
                    for(int nt=0; nt<4; nt++){
                        mma_hf(d[m][nt], A[m], &Bf[0][nt>>1][(nt&1)*2]);   // W * h_hi
                        mma_hf(d[m][nt], A[m], &Bf[1][nt>>1][(nt&1)*2]);   // W * h_lo
                    }
            }
        }
        #pragma unroll
        for(int m=0; m<2; m++)
            #pragma unroll
            for(int nt=0; nt<4; nt++){
                int mr = mw + m*16 + r4, b = nh*32 + nt*8 + c2;
                *(float2*)&acc[mr*Bb + b]     = make_float2(d[m][nt][0], d[m][nt][1]);
                *(float2*)&acc[(mr+8)*Bb + b] = make_float2(d[m][nt][2], d[m][nt][3]);
            }

        gbar(ctr, NB * (unsigned)(2*t + 1));

        // ---------- epilogue (group-local) ----------
        if(isE){
            for(int g = gbaseE; g < (Rr*Bb)/4; g += NT_E){
                int o = g*4;
                float sx=0.f, sy=0.f, sz=0.f, sw4=0.f;
                #pragma unroll
                for(int q = 0; q < 14; q++){
                    float4 a = *(const float4*)&accE[q][o];
                    sx += a.x; sy += a.y; sz += a.z; sw4 += a.w;
                }
                float4 hp = *(const float4*)&hET[o];
                float n0 = 0.7f*hp.x + 0.3f*ftanh(sx);
                float n1 = 0.7f*hp.y + 0.3f*ftanh(sy);
                float n2 = 0.7f*hp.z + 0.3f*ftanh(sz);
                float n3 = 0.7f*hp.w + 0.3f*ftanh(sw4);
                *(float4*)&hET[o] = make_float4(n0,n1,n2,n3);
                hpack4(n0,n1,n2,n3, &HEh[o], &HEl[o]);
            }
        } else {
            for(int g = gbaseG; g < (Hh*Bb)/4; g += NT_G){
                int j = g >> 4, b4 = (g & 15)*4, ix = j*64 + b4;
                float rv[4] = {0,0,0,0}, zv[4] = {0,0,0,0}, hv[4] = {0,0,0,0};
                #pragma unroll
                for(int q = 0; q < 4; q++){
                    float4 a = *(const float4*)&accRZ[q][ix];
                    float4 b = *(const float4*)&accRZ[q][(j+Hh)*64 + b4];
                    float4 h = *(const float4*)&accNH[q][ix];
                    #pragma unroll
                    for(int i=0;i<4;i++){
                        rv[i] += (&a.x)[i]; zv[i] += (&b.x)[i]; hv[i] += (&h.x)[i];
                    }
                }
                float4 x0 = *(const float4*)&accNX[0][ix];
                float4 x1 = *(const float4*)&accNX[1][ix];
                float4 hp = *(const float4*)&hGT[ix];
                float br  = bih[j] + bhh[j];
                float bz2 = bih[j+Hh] + bhh[j+Hh];
                float bxn = bih[j+2*Hh], bhn = bhh[j+2*Hh];
                float n[4];
                #pragma unroll
                for(int i=0;i<4;i++){
                    float rg = fsig(rv[i] + br);
                    float zg = fsig(zv[i] + bz2);
                    float nn = ftanh((&x0.x)[i] + (&x1.x)[i] + bxn + rg*(hv[i] + bhn));
                    n[i] = (1.0f - zg)*nn + zg*(&hp.x)[i];
                }
                *(float4*)&hGT[ix] = make_float4(n[0],n[1],n[2],n[3]);
                hpack4(n[0],n[1],n[2],n[3], &HGh[ix], &HGl[ix]);
            }
        }

        gbar(ctr, NB * (unsigned)(2*t + 2));
    }
}

// ---------------- final transpose + head ----------------
__global__ void k_tr(){
    int idx = blockIdx.x*blockDim.x + threadIdx.x;
    if(idx < Bb*Rr){ int b = idx/Rr, c = idx - b*Rr; g_hE[idx] = hET[c*Bb + b]; }
    if(idx < Bb*Hh){ int b = idx/Hh, j = idx - b*Hh; g_hG[idx] = hGT[j*Bb + b]; }
}
__global__ __launch_bounds__(256) void k_gemm(
    const float* __restrict__ A, const float* __restrict__ W,
    const float* __restrict__ bias, float* __restrict__ C, int K, int J, int act)
{
    __shared__ __align__(16) float sA[32*68];
    __shared__ float sW2[32*16];
    const int tid = threadIdx.x, tx = tid & 15, ty = tid >> 4, jb = blockIdx.x*16;
    float acc[4] = {0.f,0.f,0.f,0.f};
    for(int ch=0; ch<(K>>5); ch++){
        const int k0 = ch*32;
        #pragma unroll
        for(int r=0;r<2;r++){
            int idx = tid + r*256, b = idx>>3, kq = idx&7;
            float4 v = *(const float4*)(A + b*K + k0 + 4*kq);
            sA[(4*kq+0)*68+b]=v.x; sA[(4*kq+1)*68+b]=v.y;
            sA[(4*kq+2)*68+b]=v.z; sA[(4*kq+3)*68+b]=v.w;
        }
        #pragma unroll
        for(int r=0;r<2;r++){
            int idx = tid + r*256, kr = idx&31, c = idx>>5;
            sW2[kr*16+c] = W[(jb+c)*K + k0 + kr];
        }
        __syncthreads();
        #pragma unroll
        for(int kk=0;kk<32;kk++){
            float w = sW2[kk*16+tx];
            float4 a = *(const float4*)&sA[kk*68 + 4*ty];
            acc[0]+=a.x*w; acc[1]+=a.y*w; acc[2]+=a.z*w; acc[3]+=a.w*w;
        }
        __syncthreads();
    }
    const int j = jb + tx; const float bv = bias[j];
    #pragma unroll
    for(int i=0;i<4;i++){
        float v = acc[i] + bv;
        if(act==1) v = sigm(v); else if(act==2) v = fmaxf(v, 0.0f);
        C[(4*ty+i)*J + j] = v;
    }
}
__global__ void k_cat(){
    int idx = blockIdx.x*blockDim.x + threadIdx.x;
    if(idx < Bb*2*Hh){
        int b = idx>>10, k = idx & 1023;
        g_cat[idx] = (k < Hh) ? g_proj[b*Hh + k] : g_hG[b*Hh + (k-Hh)];
    }
}
__global__ void k_combine(){
    int idx = blockIdx.x*blockDim.x + threadIdx.x;
    if(idx < Bb*Hh){
        float g = g_gate[idx];
        g_comb[idx] = g*g_proj[idx] + (1.0f - g)*g_hG[idx];
    }
}

extern "C" void kernel_launch(void* const* d_in, const int* in_sizes, int n_in,
                              void* d_out, int out_size)
{
    const float* x     = (const float*)d_in[0];
    const float* Win   = (const float*)d_in[1];
    const float* Wres  = (const float*)d_in[2];
    const float* Wih   = (const float*)d_in[3];
    const float* Whh   = (const float*)d_in[4];
    const float* bih   = (const float*)d_in[5];
    const float* bhh   = (const float*)d_in[6];
    const float* projW = (const float*)d_in[7];
    const float* projb = (const float*)d_in[8];
    const float* gateW = (const float*)d_in[9];
    const float* gateb = (const float*)d_in[10];
    const float* hW1   = (const float*)d_in[11];
    const float* hb1   = (const float*)d_in[12];
    const float* hW2   = (const float*)d_in[13];
    const float* hb2   = (const float*)d_in[14];
    float* out = (float*)d_out;

    void *pE, *pProj, *pCat, *pComb, *pHid, *pGate;
    cudaGetSymbolAddress(&pE,    g_hE);
    cudaGetSymbolAddress(&pProj, g_proj);
    cudaGetSymbolAddress(&pCat,  g_cat);
    cudaGetSymbolAddress(&pComb, g_comb);
    cudaGetSymbolAddress(&pGate, g_gate);
    cudaGetSymbolAddress(&pHid,  g_hid);

    cudaFuncSetAttribute(k_all, cudaFuncAttributeMaxDynamicSharedMemorySize, SMEM_BYTES);

    k_prepWE<<<(Rr*KE)/256, 256>>>(Wres, Win);
    k_prepWG<<<(MG*KG)/256, 256>>>(Whh, Wih);
    k_prepXI<<<(Tt*Ii*Bb)/256, 256>>>(x);
    k_all<<<NBLK, NTHR, SMEM_BYTES>>>(bih, bhh);
    k_tr<<<512, 256>>>();
    k_gemm<<<32, 256>>>((const float*)pE,   projW, projb, (float*)pProj, Rr,   Hh, 0);
    k_cat    <<<256, 256>>>();
    k_gemm<<<32, 256>>>((const float*)pCat, gateW, gateb, (float*)pGate, 2*Hh, Hh, 1);
    k_combine<<<128, 256>>>();
    k_gemm<<<32, 256>>>((const float*)pComb, hW1,  hb1,   (float*)pHid,  Hh,   Hh, 2);
    k_gemm<<<8,  256>>>((const float*)pHid,  hW2,  hb2,   out,           Hh,   Oo, 0);
}

// round 17
// speedup vs baseline: 1.2758x; 1.2758x over previous
#include <cuda_runtime.h>
#include <cuda_fp16.h>
#include <math.h>

#define Bb 64
#define Tt 512
#define Ii 128
#define Rr 2048
#define Hh 512
#define Oo 128
#define KE 2176
#define KG 640
#define MG 1536
#define NBLK 140
#define NBE 112
#define NBG 28
#define NTHR 512
#define BCH_BYTES 9216                  // B ring chunk: k=64 = 4 subs x 2304B (fp16 single)
#define BRING_BYTES (4*BCH_BYTES)       // 36864
#define WSUB_HALFS 3072                 // W per 16-k sub: 128 rows x 24 halfs
#define SMEM_BYTES (BRING_BYTES + 20*6144)  // 159744

typedef __half hf;

// ---------------- device scratch ----------------
__device__ hf WEH[Rr*KE];                  // ESN weights^T fp16 [c][k]
__device__ hf WGH[MG*KG];                  // GRU weights^T fp16 [m][k]
__device__ hf Xq[Tt*Ii*Bb];                // x transposed fp16 [t][i][b]
__device__ hf HEq[Rr*Bb];                  // ESN state fp16 [k][b]
__device__ hf HGq[Hh*Bb];                  // GRU state fp16 [j][b]
__device__ float hET[Rr*Bb], hGT[Hh*Bb];   // fp32 states (transposed)
__device__ float accE[7][Rr*Bb];           // ESN K-split partials
__device__ float accRZ[2][1024*Bb];        // GRU r,z rows, K-split
__device__ float accNH[2][Hh*Bb];          // GRU n-gate h-part, K-split
__device__ float accNX[Hh*Bb];             // GRU n-gate x-part
__device__ unsigned g_ctrE, g_ctrG;
__device__ float g_hE[Bb*Rr], g_hG[Bb*Hh];
__device__ float g_proj[Bb*Hh], g_cat[Bb*2*Hh], g_gate[Bb*Hh], g_comb[Bb*Hh], g_hid[Bb*Hh];

__device__ __forceinline__ float sigm(float x){ return 1.0f/(1.0f+expf(-x)); }
__device__ __forceinline__ float fsig(float x){ return __fdividef(1.0f, 1.0f + __expf(-x)); }
__device__ __forceinline__ float ftanh(float x){
    float e = __expf(2.0f*x);
    return 1.0f - __fdividef(2.0f, e + 1.0f);
}
__device__ __forceinline__ unsigned hp2(hf a, hf b){
    return (unsigned)__half_as_ushort(a) | ((unsigned)__half_as_ushort(b) << 16);
}
__device__ __forceinline__ void hpack4s(float v0,float v1,float v2,float v3, hf* dst){
    *(uint2*)dst = make_uint2(hp2(__float2half_rn(v0), __float2half_rn(v1)),
                              hp2(__float2half_rn(v2), __float2half_rn(v3)));
}
__device__ __forceinline__ void ldsm4(unsigned* r, const hf* p){
    unsigned a = (unsigned)__cvta_generic_to_shared(p);
    asm volatile("ldmatrix.sync.aligned.m8n8.x4.shared.b16 {%0,%1,%2,%3},[%4];"
        : "=r"(r[0]),"=r"(r[1]),"=r"(r[2]),"=r"(r[3]) : "r"(a));
}
__device__ __forceinline__ void ldsm4t(unsigned* r, const hf* p){
    unsigned a = (unsigned)__cvta_generic_to_shared(p);
    asm volatile("ldmatrix.sync.aligned.m8n8.x4.trans.shared.b16 {%0,%1,%2,%3},[%4];"
        : "=r"(r[0]),"=r"(r[1]),"=r"(r[2]),"=r"(r[3]) : "r"(a));
}
__device__ __forceinline__ void mma_hf(float* d, const unsigned* a, const unsigned* b){
    asm volatile("mma.sync.aligned.m16n8k16.row.col.f32.f16.f16.f32 "
        "{%0,%1,%2,%3},{%4,%5,%6,%7},{%8,%9},{%0,%1,%2,%3};"
        : "+f"(d[0]),"+f"(d[1]),"+f"(d[2]),"+f"(d[3])
        : "r"(a[0]),"r"(a[1]),"r"(a[2]),"r"(a[3]),"r"(b[0]),"r"(b[1]));
}
__device__ __forceinline__ void cp16(unsigned dst, const void* src){
    asm volatile("cp.async.cg.shared.global [%0],[%1],16;" :: "r"(dst),"l"(src));
}

// ---------------- prep ----------------
__global__ void k_prepWE(const float* __restrict__ Wres, const float* __restrict__ Win){
    int idx = blockIdx.x*blockDim.x + threadIdx.x;        // c*KE + k
    int c = idx/KE, k = idx - c*KE;
    float w = (k < Rr) ? Wres[k*Rr + c] : Win[(k-Rr)*Rr + c];
    WEH[idx] = __float2half_rn(w);
}
__global__ void k_prepWG(const float* __restrict__ Whh, const float* __restrict__ Wih){
    int idx = blockIdx.x*blockDim.x + threadIdx.x;        // m*KG + k
    int m = idx/KG, k = idx - m*KG;
    float w = (k < Hh) ? Whh[m*Hh + k] : Wih[m*Ii + (k-Hh)];
    WGH[idx] = __float2half_rn(w);
}
__global__ void k_prepXI(const float* __restrict__ x){
    int idx = blockIdx.x*blockDim.x + threadIdx.x;        // t*8192 + i*64 + b
    int t = idx >> 13, r = idx & 8191, i = r >> 6, b = r & 63;
    Xq[idx] = __float2half_rn(x[b*(Tt*Ii) + t*Ii + i]);
    hf z = __float2half_rn(0.0f);
    if(idx == 0){ g_ctrE = 0u; g_ctrG = 0u; }
    if(idx < Rr*Bb){ hET[idx]=0.0f; HEq[idx]=z; }
    if(idx < Hh*Bb){ hGT[idx]=0.0f; HGq[idx]=z; }
}

__device__ __forceinline__ void gbar(unsigned* ctr, unsigned target){
    __threadfence();
    __syncthreads();
    if(threadIdx.x == 0){
        atomicAdd(ctr, 1u);
        volatile unsigned* p = ctr;
        while(*p < target) __nanosleep(32);
    }
    __syncthreads();
    __threadfence();
}

// ---------------- persistent all-timesteps kernel ----------------
// 140 blocks x 512 thr. fp16 SINGLE-product (state plain fp16).
// W persistent in smem; B ring of k=64 chunks (4 subs, 2304B each).
// Warp = (m16 slice, n32 half). Per sub: 1 ldsm + 2 ldsm.T + 4 HMMA.
// ESN group (112 blocks) and GRU group (28) sync on separate counters.
// Blocks: [0,112)  ESN: m-tile bx/7, K-split bx%7 (6x320 + 1x256) -> 5/4 chunks
//         [112,128) GRU r,z: K-split of 640 -> 5 chunks
//         [128,136) GRU n h-part: 2 splits of 512 -> 4 chunks
//         [136,140) GRU n x-part: K=[512,640) -> 2 chunks
__global__ void __launch_bounds__(NTHR) k_all(
    const float* __restrict__ bih, const float* __restrict__ bhh)
{
    extern __shared__ __align__(16) hf sm[];
    const int tid = threadIdx.x, lane = tid & 31, wid = tid >> 5, bx = blockIdx.x;
    const unsigned sb = (unsigned)__cvta_generic_to_shared(sm);
    const bool isE = (bx < NBE);

    // ---- role setup ----
    const hf *Wp, *Bq; float* acc; int Kst, kbase, nch, kth;
    if(isE){
        int m0 = (bx/7)*128, ks = bx%7;
        kbase = ks*320; nch = (ks < 6) ? 5 : 4; kth = Rr; Kst = KE;
        Wp = WEH + (size_t)m0*KE;
        Bq = HEq; acc = accE[ks] + m0*Bb;
    } else if(bx < 128){
        int g = bx-112, m0 = (g>>1)*128, ks = g&1;
        kbase = ks*320; nch = 5; kth = Hh; Kst = KG;
        Wp = WGH + (size_t)m0*KG;
        Bq = HGq; acc = accRZ[ks] + m0*Bb;
    } else if(bx < 136){
        int g = bx-128, mt = g>>1, ks = g&1;
        kbase = ks*256; nch = 4; kth = Hh; Kst = KG;
        Wp = WGH + (size_t)(1024 + mt*128)*KG;
        Bq = HGq; acc = accNH[ks] + mt*128*Bb;
    } else {
        int mt = bx-136;
        kbase = 512; nch = 2; kth = Hh; Kst = KG;
        Wp = WGH + (size_t)(1024 + mt*128)*KG;
        Bq = HGq; acc = accNX + mt*128*Bb;
    }
    unsigned* ctr = isE ? &g_ctrE : &g_ctrG;
    const unsigned NB = isE ? NBE : NBG;

    // ---- one-time W prologue: nch*4 subs, each 128 rows x 24-half stride ----
    {
        const int nsubs = nch*4;
        int rp = tid & 255, row = rp >> 1, part = rp & 1;
        for(int s2 = 0; s2 < nsubs; s2 += 2){
            int sub = s2 + (tid >> 8);
            if(sub < nsubs)
                cp16(sb + (unsigned)BRING_BYTES + (unsigned)(sub*6144 + row*48 + part*16),
                     Wp + (size_t)row*Kst + kbase + sub*16 + part*8);
        }
        asm volatile("cp.async.commit_group;");
        asm volatile("cp.async.wait_group 0;");
        __syncthreads();
    }

    // ---- B loader: 512 threads cover one k=64 chunk (4 subs x 128 thr) ----
    const int bsub = tid >> 7, btid = tid & 127;
    const int krow = btid >> 3, boff = (btid & 7) * 8;
    const unsigned bd0 = sb + (unsigned)(bsub*2304 + krow*144 + (btid&7)*16);

    // ---- warp tiling: warp = (m16 slice, n32 half) ----
    const int mw = (wid >> 1) * 16, nh = wid & 1;
    const int ar = lane & 15, ac = (lane>>4)*8;
    const int r4 = lane>>2, c2 = 2*(lane&3);
    const int gbaseE = bx*NTHR + tid;
    const int gbaseG = (bx - NBE)*NTHR + tid;
    const int NT_E = NBE*NTHR, NT_G = NBG*NTHR;

    for(int t = 0; t < Tt; t++){
        const hf* Xt = Xq + (size_t)t*Ii*Bb;

        auto issue = [&](int c){
            if(c >= nch) return;
            int kr = kbase + c*64 + bsub*16 + krow;
            const hf* q = (kr < kth) ? Bq + kr*Bb + boff : Xt + (kr-kth)*Bb + boff;
            cp16(bd0 + (unsigned)(c & 3)*BCH_BYTES, q);
            asm volatile("cp.async.commit_group;");
        };

        float d[4][4];
        #pragma unroll
        for(int j=0;j<4;j++)
            #pragma unroll
            for(int q=0;q<4;q++) d[j][q] = 0.0f;

        issue(0); issue(1); issue(2);

        for(int c = 0; c < nch; c++){
            if(c < nch-2)       asm volatile("cp.async.wait_group 2;");
            else if(c == nch-2) asm volatile("cp.async.wait_group 1;");
            else                asm volatile("cp.async.wait_group 0;");
            __syncthreads();
            if(c + 3 < nch) issue(c + 3);

            #pragma unroll
            for(int sub = 0; sub < 4; ++sub){
                const hf* sw = sm + (BRING_BYTES/2) + (size_t)(c*4 + sub)*WSUB_HALFS;
                const hf* sB = sm + (size_t)(c & 3)*(BCH_BYTES/2) + sub*1152;

                unsigned A[4], Bf[2][4];
                ldsm4(A, sw + (mw + ar)*24 + ac);
                ldsm4t(Bf[0], sB + ar*72 + (2*nh + 0)*16 + ac);
                ldsm4t(Bf[1], sB + ar*72 + (2*nh + 1)*16 + ac);
                #pragma unroll
                for(int nt=0; nt<4; nt++)
                    mma_hf(d[nt], A, &Bf[nt>>1][(nt&1)*2]);
            }
        }
        #pragma unroll
        for(int nt=0; nt<4; nt++){
            int m = mw + r4, b = nh*32 + nt*8 + c2;
            *(float2*)&acc[m*Bb + b]     = make_float2(d[nt][0], d[nt][1]);
            *(float2*)&acc[(m+8)*Bb + b] = make_float2(d[nt][2], d[nt][3]);
        }

        gbar(ctr, NB * (unsigned)(2*t + 1));

        // ---------- epilogue (group-local) ----------
        if(isE){
            for(int g = gbaseE; g < (Rr*Bb)/4; g += NT_E){
                int o = g*4;
                float4 a0 = *(const float4*)&accE[0][o];
                float4 a1 = *(const float4*)&accE[1][o];
                float4 a2 = *(const float4*)&accE[2][o];
                float4 a3 = *(const float4*)&accE[3][o];
                float4 a4 = *(const float4*)&accE[4][o];
                float4 a5 = *(const float4*)&accE[5][o];
                float4 a6 = *(const float4*)&accE[6][o];
                float4 hp = *(const float4*)&hET[o];
                float n0 = 0.7f*hp.x + 0.3f*ftanh(a0.x+a1.x+a2.x+a3.x+a4.x+a5.x+a6.x);
                float n1 = 0.7f*hp.y + 0.3f*ftanh(a0.y+a1.y+a2.y+a3.y+a4.y+a5.y+a6.y);
                float n2 = 0.7f*hp.z + 0.3f*ftanh(a0.z+a1.z+a2.z+a3.z+a4.z+a5.z+a6.z);
                float n3 = 0.7f*hp.w + 0.3f*ftanh(a0.w+a1.w+a2.w+a3.w+a4.w+a5.w+a6.w);
                *(float4*)&hET[o] = make_float4(n0,n1,n2,n3);
                hpack4s(n0,n1,n2,n3, &HEq[o]);
            }
        } else {
            for(int g = gbaseG; g < (Hh*Bb)/4; g += NT_G){
                int j = g >> 4, b4 = (g & 15)*4, ix = j*64 + b4;
                float4 r0 = *(const float4*)&accRZ[0][ix];
                float4 r1 = *(const float4*)&accRZ[1][ix];
                float4 z0 = *(const float4*)&accRZ[0][(j+Hh)*64 + b4];
                float4 z1 = *(const float4*)&accRZ[1][(j+Hh)*64 + b4];
                float4 h0 = *(const float4*)&accNH[0][ix];
                float4 h1 = *(const float4*)&accNH[1][ix];
                float4 xn = *(const float4*)&accNX[ix];
                float4 hp = *(const float4*)&hGT[ix];
                float br  = bih[j] + bhh[j];
                float bz2 = bih[j+Hh] + bhh[j+Hh];
                float bxn = bih[j+2*Hh], bhn = bhh[j+2*Hh];
                float n[4];
                #pragma unroll
                for(int i=0;i<4;i++){
                    float rv = (&r0.x)[i] + (&r1.x)[i];
                    float zv = (&z0.x)[i] + (&z1.x)[i];
                    float hnv = (&h0.x)[i] + (&h1.x)[i];
                    float rg = fsig(rv + br);
                    float zg = fsig(zv + bz2);
                    float nn = ftanh((&xn.x)[i] + bxn + rg*(hnv + bhn));
                    n[i] = (1.0f - zg)*nn + zg*(&hp.x)[i];
                }
                *(float4*)&hGT[ix] = make_float4(n[0],n[1],n[2],n[3]);
                hpack4s(n[0],n[1],n[2],n[3], &HGq[ix]);
            }
        }

        gbar(ctr, NB * (unsigned)(2*t + 2));
    }
}

// ---------------- final transpose + head ----------------
__global__ void k_tr(){
    int idx = blockIdx.x*blockDim.x + threadIdx.x;
    if(idx < Bb*Rr){ int b = idx/Rr, c = idx - b*Rr; g_hE[idx] = hET[c*Bb + b]; }
    if(idx < Bb*Hh){ int b = idx/Hh, j = idx - b*Hh; g_hG[idx] = hGT[j*Bb + b]; }
}
__global__ __launch_bounds__(256) void k_gemm(
    const float* __restrict__ A, const float* __restrict__ W,
    const float* __restrict__ bias, float* __restrict__ C, int K, int J, int act)
{
    __shared__ __align__(16) float sA[32*68];
    __shared__ float sW2[32*16];
    const int tid = threadIdx.x, tx = tid & 15, ty = tid >> 4, jb = blockIdx.x*16;
    float acc[4] = {0.f,0.f,0.f,0.f};
    for(int ch=0; ch<(K>>5); ch++){
        const int k0 = ch*32;
        #pragma unroll
        for(int r=0;r<2;r++){
            int idx = tid + r*256, b = idx>>3, kq = idx&7;
            float4 v = *(const float4*)(A + b*K + k0 + 4*kq);
            sA[(4*kq+0)*68+b]=v.x; sA[(4*kq+1)*68+b]=v.y;
            sA[(4*kq+2)*68+b]=v.z; sA[(4*kq+3)*68+b]=v.w;
        }
        #pragma unroll
        for(int r=0;r<2;r++){
            int idx = tid + r*256, kr = idx&31, c = idx>>5;
            sW2[kr*16+c] = W[(jb+c)*K + k0 + kr];
        }
        __syncthreads();
        #pragma unroll
        for(int kk=0;kk<32;kk++){
            float w = sW2[kk*16+tx];
            float4 a = *(const float4*)&sA[kk*68 + 4*ty];
            acc[0]+=a.x*w; acc[1]+=a.y*w; acc[2]+=a.z*w; acc[3]+=a.w*w;
        }
        __syncthreads();
    }
    const int j = jb + tx; const float bv = bias[j];
    #pragma unroll
    for(int i=0;i<4;i++){
        float v = acc[i] + bv;
        if(act==1) v = sigm(v); else if(act==2) v = fmaxf(v, 0.0f);
        C[(4*ty+i)*J + j] = v;
    }
}
__global__ void k_cat(){
    int idx = blockIdx.x*blockDim.x + threadIdx.x;
    if(idx < Bb*2*Hh){
        int b = idx>>10, k = idx & 1023;
        g_cat[idx] = (k < Hh) ? g_proj[b*Hh + k] : g_hG[b*Hh + (k-Hh)];
    }
}
__global__ void k_combine(){
    int idx = blockIdx.x*blockDim.x + threadIdx.x;
    if(idx < Bb*Hh){
        float g = g_gate[idx];
        g_comb[idx] = g*g_proj[idx] + (1.0f - g)*g_hG[idx];
    }
}

extern "C" void kernel_launch(void* const* d_in, const int* in_sizes, int n_in,
                              void* d_out, int out_size)
{
    const float* x     = (const float*)d_in[0];
    const float* Win   = (const float*)d_in[1];
    const float* Wres  = (const float*)d_in[2];
    const float* Wih   = (const float*)d_in[3];
    const float* Whh   = (const float*)d_in[4];
    const float* bih   = (const float*)d_in[5];
    const float* bhh   = (const float*)d_in[6];
    const float* projW = (const float*)d_in[7];
    const float* projb = (const float*)d_in[8];
    const float* gateW = (const float*)d_in[9];
    const float* gateb = (const float*)d_in[10];
    const float* hW1   = (const float*)d_in[11];
    const float* hb1   = (const float*)d_in[12];
    const float* hW2   = (const float*)d_in[13];
    const float* hb2   = (const float*)d_in[14];
    float* out = (float*)d_out;

    void *pE, *pProj, *pCat, *pComb, *pHid, *pGate;
    cudaGetSymbolAddress(&pE,    g_hE);
    cudaGetSymbolAddress(&pProj, g_proj);
    cudaGetSymbolAddress(&pCat,  g_cat);
    cudaGetSymbolAddress(&pComb, g_comb);
    cudaGetSymbolAddress(&pGate, g_gate);
    cudaGetSymbolAddress(&pHid,  g_hid);

    cudaFuncSetAttribute(k_all, cudaFuncAttributeMaxDynamicSharedMemorySize, SMEM_BYTES);

    k_prepWE<<<(Rr*KE)/256, 256>>>(Wres, Win);
    k_prepWG<<<(MG*KG)/256, 256>>>(Whh, Wih);
    k_prepXI<<<(Tt*Ii*Bb)/256, 256>>>(x);
    k_all<<<NBLK, NTHR, SMEM_BYTES>>>(bih, bhh);
    k_tr<<<512, 256>>>();
    k_gemm<<<32, 256>>>((const float*)pE,   projW, projb, (float*)pProj, Rr,   Hh, 0);
    k_cat    <<<256, 256>>>();
    k_gemm<<<32, 256>>>((const float*)pCat, gateW, gateb, (float*)pGate, 2*Hh, Hh, 1);
    k_combine<<<128, 256>>>();
    k_gemm<<<32, 256>>>((const float*)pComb, hW1,  hb1,   (float*)pHid,  Hh,   Hh, 2);
    k_gemm<<<8,  256>>>((const float*)pHid,  hW2,  hb2,   out,           Hh,   Oo, 0);
}